// round 14
// baseline (speedup 1.0000x reference)
#include <cuda_runtime.h>
#include <cuda_fp16.h>
#include <math.h>
#include <stdint.h>

// Problem constants
#define BATCH 16
#define THW   2048
#define TF    2048
#define CDIM  512

#define NELEM_QK (BATCH * THW * CDIM)
#define NELEM_SC ((size_t)BATCH * THW * (size_t)TF)

// ---------------------------------------------------------------------------
// Scratch (device globals — no allocations allowed)
// ---------------------------------------------------------------------------
__device__ float g_qin[NELEM_QK];                 // fp32 q-projection (residual)
__device__ float g_sc [NELEM_SC];                 // fp32 scores
__device__ __half g_qh [NELEM_QK], g_ql [NELEM_QK];
__device__ __half g_kh [NELEM_QK], g_kl [NELEM_QK];
__device__ __half g_Wqh[CDIM*CDIM], g_Wql[CDIM*CDIM];
__device__ __half g_Wkh[CDIM*CDIM], g_Wkl[CDIM*CDIM];
__device__ __half g_Wvh[CDIM*CDIM], g_Wvl[CDIM*CDIM];
__device__ __half g_qinh[NELEM_QK], g_qinl[NELEM_QK];
__device__ __half g_kph [NELEM_QK], g_kpl [NELEM_QK]; // [b][t][c]
__device__ __half g_vph [NELEM_QK];                   // [b][t][c] hi only
__device__ __half g_sch [NELEM_SC];                   // fp16 attn (1-pass output)

// ---------------------------------------------------------------------------
// GEMM config: 128x128 tile, BK=32, 256 threads = 8 warps (2m x 4n),
// warp tile 64x32. 2 CTAs/SM (reg cap 128) + NSTG-stage cp.async pipeline.
// NPASS: 3 = AhBh+AhBl+AlBh, 2 = AhBh+AlBh, 1 = AhBh.
// Stage layout is compact per NPASS: [Ah][Al?][Bh][Bl?].
// B operand convention: B[k][n], row stride ldb (k-major).
// ---------------------------------------------------------------------------
#define BK 32
#define LDA_S 40                    // padded A row stride (halves)
#define LDB_S 136                   // padded B row stride (halves)
#define A_HB (128 * LDA_S * 2)      // 10240 bytes per A half-tile
#define B_HB (BK * LDB_S * 2)       // 8704 bytes per B half-tile

__device__ __forceinline__ void ldsm4(uint32_t* r, uint32_t addr) {
    asm volatile("ldmatrix.sync.aligned.m8n8.x4.shared.b16 {%0,%1,%2,%3}, [%4];\n"
                 : "=r"(r[0]), "=r"(r[1]), "=r"(r[2]), "=r"(r[3]) : "r"(addr));
}
__device__ __forceinline__ void ldsm4t(uint32_t* r, uint32_t addr) {
    asm volatile("ldmatrix.sync.aligned.m8n8.x4.trans.shared.b16 {%0,%1,%2,%3}, [%4];\n"
                 : "=r"(r[0]), "=r"(r[1]), "=r"(r[2]), "=r"(r[3]) : "r"(addr));
}
__device__ __forceinline__ void mma16816(float* c, const uint32_t* a, const uint32_t* b) {
    asm volatile("mma.sync.aligned.m16n8k16.row.col.f32.f16.f16.f32 "
                 "{%0,%1,%2,%3},{%4,%5,%6,%7},{%8,%9},{%0,%1,%2,%3};\n"
                 : "+f"(c[0]), "+f"(c[1]), "+f"(c[2]), "+f"(c[3])
                 : "r"(a[0]), "r"(a[1]), "r"(a[2]), "r"(a[3]), "r"(b[0]), "r"(b[1]));
}
__device__ __forceinline__ void cp16(uint32_t dst, const void* src) {
    asm volatile("cp.async.cg.shared.global [%0], [%1], 16;\n" :: "r"(dst), "l"(src));
}
__device__ __forceinline__ void cp_commit() {
    asm volatile("cp.async.commit_group;\n" ::: "memory");
}
template <int N>
__device__ __forceinline__ void cp_wait() {
    asm volatile("cp.async.wait_group %0;\n" :: "n"(N) : "memory");
}

template <int NPASS, int NSTG>
__global__ __launch_bounds__(256, 2) void mma_gemm(
    const __half* __restrict__ Ahg, const __half* __restrict__ Alg,
    const __half* __restrict__ Bhg, const __half* __restrict__ Blg,
    const float* __restrict__ bias, const float* __restrict__ resid,
    float* __restrict__ Cf, __half* __restrict__ Ch, __half* __restrict__ Cl,
    int K, int lda, int ldb, int ldc,
    long long sA, long long sB, long long sC, long long sR)
{
    constexpr bool USE_AL = (NPASS >= 2);   // P3: Al*Bh
    constexpr bool USE_BL = (NPASS >= 3);   // P2: Ah*Bl
    constexpr uint32_t A_SEC = A_HB * (USE_AL ? 2 : 1);
    constexpr uint32_t B_SEC = B_HB * (USE_BL ? 2 : 1);
    constexpr uint32_t STAGE = A_SEC + B_SEC;
    constexpr uint32_t OFF_AL = A_HB;
    constexpr uint32_t OFF_BH = A_SEC;
    constexpr uint32_t OFF_BL = A_SEC + B_HB;

    extern __shared__ char smem[];
    const uint32_t smem_u32 = (uint32_t)__cvta_generic_to_shared(smem);

    const long long bz = blockIdx.z;
    Ahg += bz * sA; if (USE_AL) Alg += bz * sA;
    Bhg += bz * sB; if (USE_BL) Blg += bz * sB;
    if (Cf)    Cf    += bz * sC;
    if (Ch)    Ch    += bz * sC;
    if (Cl)    Cl    += bz * sC;
    if (resid) resid += bz * sR;

    const int tid  = threadIdx.x;
    const int warp = tid >> 5;
    const int lane = tid & 31;
    const int wm = warp >> 2;
    const int wn = warp & 3;
    const int g   = lane >> 2;
    const int tig = lane & 3;

    const int row0 = blockIdx.y * 128;
    const int col0 = blockIdx.x * 128;

    // cp.async load maps: A half-tile 128x32 half = 64B/row, 2 threads/row
    const int ar  = tid >> 1;            // 0..127
    const int ab  = (tid & 1) * 32;      // byte offset {0,32}, +16 inner
    // B half-tile 32x128 half = 256B/row, 8 threads/row
    const int br  = tid >> 3;            // 0..31
    const int bb  = (tid & 7) * 32;      // byte offset, +16 inner

    // ldmatrix fragment address components (verified R4/R8)
    const int a_r = wm * 64 + (lane & 15);
    const int a_c = (lane >> 4) * 8;
    const int b_r = lane & 15;
    const int b_c = wn * 32 + ((lane & 16) ? 8 : 0);

    float acc[4][4][4];
    #pragma unroll
    for (int i = 0; i < 4; i++)
        #pragma unroll
        for (int j = 0; j < 4; j++)
            #pragma unroll
            for (int l = 0; l < 4; l++) acc[i][j][l] = 0.0f;

    const int NC = K / BK;

    auto load_stage = [&](int stage, int chunk) {
        const uint32_t sb = smem_u32 + stage * STAGE;
        const int k0 = chunk * BK;
        #pragma unroll
        for (int i = 0; i < 2; i++) {
            const long long ao = (long long)(row0 + ar) * lda + k0 + (ab >> 1) + i * 8;
            const uint32_t ad = sb + ar * (LDA_S * 2) + ab + i * 16;
            cp16(ad, Ahg + ao);
            if (USE_AL) cp16(ad + OFF_AL, Alg + ao);
        }
        #pragma unroll
        for (int i = 0; i < 2; i++) {
            const long long bo = (long long)(k0 + br) * ldb + col0 + (bb >> 1) + i * 8;
            const uint32_t bd = sb + OFF_BH + br * (LDB_S * 2) + bb + i * 16;
            cp16(bd, Bhg + bo);
            if (USE_BL) cp16(bd + B_HB, Blg + bo);
        }
    };

    // prologue: fill NSTG-1 stages
    #pragma unroll
    for (int s = 0; s < NSTG - 1; s++) {
        if (s < NC) load_stage(s, s);
        cp_commit();
    }

    for (int c = 0; c < NC; c++) {
        // chunk c resident when <= NSTG-2 newer groups pending (tail: 0)
        if (c + NSTG - 1 < NC) cp_wait<NSTG - 2>(); else cp_wait<0>();
        __syncthreads();    // all warps past chunk c-(NSTG-1)'s buffer; c visible

        if (c + NSTG - 1 < NC) {
            load_stage((c + NSTG - 1) % NSTG, c + NSTG - 1);
            cp_commit();
        }

        const uint32_t sb  = smem_u32 + (c % NSTG) * STAGE;
        const uint32_t ah0 = sb;
        const uint32_t al0 = sb + OFF_AL;
        const uint32_t bh0 = sb + OFF_BH;
        const uint32_t bl0 = sb + OFF_BL;

        #pragma unroll
        for (int ks = 0; ks < 2; ks++) {
            uint32_t fah[4][4], fbh[4][2];
            #pragma unroll
            for (int mt = 0; mt < 4; mt++)
                ldsm4(fah[mt], ah0 + 2 * ((a_r + mt * 16) * LDA_S + a_c + ks * 16));
            {
                uint32_t t[4];
                ldsm4t(t, bh0 + 2 * ((ks * 16 + b_r) * LDB_S + b_c));
                fbh[0][0] = t[0]; fbh[0][1] = t[1]; fbh[1][0] = t[2]; fbh[1][1] = t[3];
                ldsm4t(t, bh0 + 2 * ((ks * 16 + b_r) * LDB_S + b_c + 16));
                fbh[2][0] = t[0]; fbh[2][1] = t[1]; fbh[3][0] = t[2]; fbh[3][1] = t[3];
            }
            // P1: Ah * Bh
            #pragma unroll
            for (int mt = 0; mt < 4; mt++)
                #pragma unroll
                for (int nt = 0; nt < 4; nt++)
                    mma16816(acc[mt][nt], fah[mt], fbh[nt]);

            // P2: Ah * Bl (scoped fragments — keep reg count low)
            if (USE_BL) {
                uint32_t fbl[4][2];
                uint32_t t[4];
                ldsm4t(t, bl0 + 2 * ((ks * 16 + b_r) * LDB_S + b_c));
                fbl[0][0] = t[0]; fbl[0][1] = t[1]; fbl[1][0] = t[2]; fbl[1][1] = t[3];
                ldsm4t(t, bl0 + 2 * ((ks * 16 + b_r) * LDB_S + b_c + 16));
                fbl[2][0] = t[0]; fbl[2][1] = t[1]; fbl[3][0] = t[2]; fbl[3][1] = t[3];
                #pragma unroll
                for (int mt = 0; mt < 4; mt++)
                    #pragma unroll
                    for (int nt = 0; nt < 4; nt++)
                        mma16816(acc[mt][nt], fah[mt], fbl[nt]);
            }
            // P3: Al * Bh (one A-fragment at a time)
            if (USE_AL) {
                uint32_t fal[4];
                #pragma unroll
                for (int mt = 0; mt < 4; mt++) {
                    ldsm4(fal, al0 + 2 * ((a_r + mt * 16) * LDA_S + a_c + ks * 16));
                    #pragma unroll
                    for (int nt = 0; nt < 4; nt++)
                        mma16816(acc[mt][nt], fal, fbh[nt]);
                }
            }
        }
    }

    // ---- epilogue (mapping verified R4/R8) ----
    #pragma unroll
    for (int mt = 0; mt < 4; mt++) {
        #pragma unroll
        for (int nt = 0; nt < 4; nt++) {
            const int r = row0 + wm * 64 + mt * 16 + g;
            const int c = col0 + wn * 32 + nt * 8 + 2 * tig;
            float2 v0 = make_float2(acc[mt][nt][0], acc[mt][nt][1]);
            float2 v1 = make_float2(acc[mt][nt][2], acc[mt][nt][3]);
            if (bias) {
                const float b0 = bias[c], b1 = bias[c + 1];
                v0.x += b0; v0.y += b1;
                v1.x += b0; v1.y += b1;
            }
            if (resid) {
                const float2 r0v = *reinterpret_cast<const float2*>(&resid[(long long)r * ldc + c]);
                const float2 r1v = *reinterpret_cast<const float2*>(&resid[(long long)(r + 8) * ldc + c]);
                v0.x += r0v.x; v0.y += r0v.y;
                v1.x += r1v.x; v1.y += r1v.y;
            }
            if (Cf) {
                *reinterpret_cast<float2*>(&Cf[(long long)r * ldc + c]) = v0;
                *reinterpret_cast<float2*>(&Cf[(long long)(r + 8) * ldc + c]) = v1;
            }
            if (Ch) {
                const __half h0 = __float2half_rn(v0.x);
                const __half h1 = __float2half_rn(v0.y);
                const __half h2 = __float2half_rn(v1.x);
                const __half h3 = __float2half_rn(v1.y);
                *reinterpret_cast<__half2*>(&Ch[(long long)r * ldc + c]) =
                    __halves2half2(h0, h1);
                *reinterpret_cast<__half2*>(&Ch[(long long)(r + 8) * ldc + c]) =
                    __halves2half2(h2, h3);
                if (Cl) {
                    *reinterpret_cast<__half2*>(&Cl[(long long)r * ldc + c]) =
                        __halves2half2(__float2half_rn(v0.x - __half2float(h0)),
                                       __float2half_rn(v0.y - __half2float(h1)));
                    *reinterpret_cast<__half2*>(&Cl[(long long)(r + 8) * ldc + c]) =
                        __halves2half2(__float2half_rn(v1.x - __half2float(h2)),
                                       __float2half_rn(v1.y - __half2float(h3)));
                }
            }
        }
    }
}

// ---------------------------------------------------------------------------
// fp32 -> fp16 hi/lo elementwise split
// ---------------------------------------------------------------------------
__global__ __launch_bounds__(256) void split_kernel(
    const float* __restrict__ x, __half* __restrict__ h,
    __half* __restrict__ l, int n4)
{
    const int idx = blockIdx.x * 256 + threadIdx.x;
    if (idx >= n4) return;
    const float4 v = reinterpret_cast<const float4*>(x)[idx];
    const __half h0 = __float2half_rn(v.x), h1 = __float2half_rn(v.y);
    const __half h2 = __float2half_rn(v.z), h3 = __float2half_rn(v.w);
    reinterpret_cast<__half2*>(h)[idx * 2]     = __halves2half2(h0, h1);
    reinterpret_cast<__half2*>(h)[idx * 2 + 1] = __halves2half2(h2, h3);
    reinterpret_cast<__half2*>(l)[idx * 2] = __halves2half2(
        __float2half_rn(v.x - __half2float(h0)),
        __float2half_rn(v.y - __half2float(h1)));
    reinterpret_cast<__half2*>(l)[idx * 2 + 1] = __halves2half2(
        __float2half_rn(v.z - __half2float(h2)),
        __float2half_rn(v.w - __half2float(h3)));
}

// ---------------------------------------------------------------------------
// Row softmax over TF, fp16 output (output GEMM is 1-pass)
// ---------------------------------------------------------------------------
__global__ __launch_bounds__(256) void softmax_h(
    const float* __restrict__ S, __half* __restrict__ H)
{
    const long long row = blockIdx.x;
    const float* p = S + row * (long long)TF;
    const int tid = threadIdx.x;
    __shared__ float red[32];

    float4 v0 = *reinterpret_cast<const float4*>(&p[tid * 8]);
    float4 v1 = *reinterpret_cast<const float4*>(&p[tid * 8 + 4]);

    float lmax = fmaxf(fmaxf(fmaxf(v0.x, v0.y), fmaxf(v0.z, v0.w)),
                       fmaxf(fmaxf(v1.x, v1.y), fmaxf(v1.z, v1.w)));
    #pragma unroll
    for (int o = 16; o; o >>= 1) lmax = fmaxf(lmax, __shfl_xor_sync(0xffffffffu, lmax, o));
    if ((tid & 31) == 0) red[tid >> 5] = lmax;
    __syncthreads();
    if (tid < 32) {
        float v = (tid < 8) ? red[tid] : -INFINITY;
        #pragma unroll
        for (int o = 4; o; o >>= 1) v = fmaxf(v, __shfl_xor_sync(0xffffffffu, v, o));
        if (tid == 0) red[0] = v;
    }
    __syncthreads();
    const float mx = red[0];
    __syncthreads();

    v0.x = __expf(v0.x - mx); v0.y = __expf(v0.y - mx);
    v0.z = __expf(v0.z - mx); v0.w = __expf(v0.w - mx);
    v1.x = __expf(v1.x - mx); v1.y = __expf(v1.y - mx);
    v1.z = __expf(v1.z - mx); v1.w = __expf(v1.w - mx);
    float lsum = (v0.x + v0.y + v0.z + v0.w) + (v1.x + v1.y + v1.z + v1.w);
    #pragma unroll
    for (int o = 16; o; o >>= 1) lsum += __shfl_xor_sync(0xffffffffu, lsum, o);
    if ((tid & 31) == 0) red[tid >> 5] = lsum;
    __syncthreads();
    if (tid < 32) {
        float v = (tid < 8) ? red[tid] : 0.0f;
        #pragma unroll
        for (int o = 4; o; o >>= 1) v += __shfl_xor_sync(0xffffffffu, v, o);
        if (tid == 0) red[0] = v;
    }
    __syncthreads();
    const float inv = 1.0f / red[0];

    __half* hp = H + row * (long long)TF + tid * 8;
    *reinterpret_cast<__half2*>(hp)     = __halves2half2(__float2half_rn(v0.x * inv), __float2half_rn(v0.y * inv));
    *reinterpret_cast<__half2*>(hp + 2) = __halves2half2(__float2half_rn(v0.z * inv), __float2half_rn(v0.w * inv));
    *reinterpret_cast<__half2*>(hp + 4) = __halves2half2(__float2half_rn(v1.x * inv), __float2half_rn(v1.y * inv));
    *reinterpret_cast<__half2*>(hp + 6) = __halves2half2(__float2half_rn(v1.z * inv), __float2half_rn(v1.w * inv));
}

// ---------------------------------------------------------------------------
// kernel_launch
// ---------------------------------------------------------------------------
extern "C" void kernel_launch(void* const* d_in, const int* in_sizes, int n_in,
                              void* d_out, int out_size)
{
    const float* q  = (const float*)d_in[0];
    const float* k  = (const float*)d_in[1];
    const float* Wq = (const float*)d_in[2];
    const float* bq = (const float*)d_in[3];
    const float* Wk = (const float*)d_in[4];
    const float* bk = (const float*)d_in[5];
    const float* Wv = (const float*)d_in[6];
    const float* bv = (const float*)d_in[7];
    float* out = (float*)d_out;

    void* p;
    cudaGetSymbolAddress(&p, g_qin);  float* qin = (float*)p;
    cudaGetSymbolAddress(&p, g_sc);   float* sc  = (float*)p;
    cudaGetSymbolAddress(&p, g_qh);   __half* qh = (__half*)p;
    cudaGetSymbolAddress(&p, g_ql);   __half* ql = (__half*)p;
    cudaGetSymbolAddress(&p, g_kh);   __half* kh = (__half*)p;
    cudaGetSymbolAddress(&p, g_kl);   __half* kl = (__half*)p;
    cudaGetSymbolAddress(&p, g_Wqh);  __half* Wqh = (__half*)p;
    cudaGetSymbolAddress(&p, g_Wql);  __half* Wql = (__half*)p;
    cudaGetSymbolAddress(&p, g_Wkh);  __half* Wkh = (__half*)p;
    cudaGetSymbolAddress(&p, g_Wkl);  __half* Wkl = (__half*)p;
    cudaGetSymbolAddress(&p, g_Wvh);  __half* Wvh = (__half*)p;
    cudaGetSymbolAddress(&p, g_Wvl);  __half* Wvl = (__half*)p;
    cudaGetSymbolAddress(&p, g_qinh); __half* qinh = (__half*)p;
    cudaGetSymbolAddress(&p, g_qinl); __half* qinl = (__half*)p;
    cudaGetSymbolAddress(&p, g_kph);  __half* kph  = (__half*)p;
    cudaGetSymbolAddress(&p, g_kpl);  __half* kpl  = (__half*)p;
    cudaGetSymbolAddress(&p, g_vph);  __half* vph  = (__half*)p;
    cudaGetSymbolAddress(&p, g_sch);  __half* sch  = (__half*)p;

    // Stage sizes per NPASS (must match kernel constexpr)
    const int ST3 = 2 * A_HB + 2 * B_HB;   // 37888
    const int ST2 = 2 * A_HB + B_HB;       // 29184
    const int ST1 = A_HB + B_HB;           // 18944

    // 3-stage for the 3-pass kernel only if 2 CTAs x 3 stages fit per SM
    int smem_sm = 0;
    cudaDeviceGetAttribute(&smem_sm, cudaDevAttrMaxSharedMemoryPerMultiprocessor, 0);
    const bool big3 = (2 * 3 * ST3 + 4096) <= smem_sm;

    cudaFuncSetAttribute(mma_gemm<3,3>, cudaFuncAttributeMaxDynamicSharedMemorySize, 3 * ST3);
    cudaFuncSetAttribute(mma_gemm<3,2>, cudaFuncAttributeMaxDynamicSharedMemorySize, 2 * ST3);
    cudaFuncSetAttribute(mma_gemm<2,3>, cudaFuncAttributeMaxDynamicSharedMemorySize, 3 * ST2);
    cudaFuncSetAttribute(mma_gemm<1,3>, cudaFuncAttributeMaxDynamicSharedMemorySize, 3 * ST1);

    auto launch3 = [&](dim3 grd,
                       const __half* Ah, const __half* Al,
                       const __half* Bh, const __half* Bl,
                       const float* bias, const float* resid,
                       float* Cf, __half* Ch, __half* Cl,
                       int K, int lda, int ldb, int ldc,
                       long long sA, long long sB, long long sC, long long sR) {
        if (big3)
            mma_gemm<3,3><<<grd, 256, 3 * ST3>>>(Ah, Al, Bh, Bl, bias, resid,
                                                 Cf, Ch, Cl, K, lda, ldb, ldc,
                                                 sA, sB, sC, sR);
        else
            mma_gemm<3,2><<<grd, 256, 2 * ST3>>>(Ah, Al, Bh, Bl, bias, resid,
                                                 Cf, Ch, Cl, K, lda, ldb, ldc,
                                                 sA, sB, sC, sR);
    };

    // 1. split inputs + weights to fp16 hi/lo
    {
        const int n4 = NELEM_QK / 4;
        split_kernel<<<n4 / 256, 256>>>(q, qh, ql, n4);
        split_kernel<<<n4 / 256, 256>>>(k, kh, kl, n4);
        const int w4 = CDIM * CDIM / 4;
        split_kernel<<<w4 / 256, 256>>>(Wq, Wqh, Wql, w4);
        split_kernel<<<w4 / 256, 256>>>(Wk, Wkh, Wkl, w4);
        split_kernel<<<w4 / 256, 256>>>(Wv, Wvh, Wvl, w4);
    }
    // 2. projections: q,k 3-pass; v 2-pass  (B = W[k][n], ldb = CDIM)
    {
        const dim3 grd(CDIM / 128, (BATCH * THW) / 128, 1);
        launch3(grd, qh, ql, Wqh, Wql, bq, nullptr, qin, qinh, qinl,
                CDIM, CDIM, CDIM, CDIM, 0, 0, 0, 0);
        launch3(grd, kh, kl, Wkh, Wkl, bk, nullptr, nullptr, kph, kpl,
                CDIM, CDIM, CDIM, CDIM, 0, 0, 0, 0);
        mma_gemm<2,3><<<grd, 256, 3 * ST2>>>(kh, kl, Wvh, nullptr, bv, nullptr,
                                             nullptr, vph, nullptr,
                                             CDIM, CDIM, CDIM, CDIM, 0, 0, 0, 0);
    }
    // 3. scores (3-pass): qin (lda=CDIM) x raw-view kin[c][t] (B[k=c][n=t], ldb=TF)
    {
        const dim3 grd(TF / 128, THW / 128, BATCH);
        launch3(grd, qinh, qinl, kph, kpl, nullptr, nullptr, sc, nullptr, nullptr,
                CDIM, CDIM, TF, TF,
                (long long)THW * CDIM,
                (long long)TF * CDIM,
                (long long)THW * TF, 0);
    }
    // 4. softmax -> fp16
    softmax_h<<<BATCH * THW, 256>>>(sc, sch);
    // 5. output (1-pass fp16): attn (lda=TF) x vp[t][c] (B[k=t][n=c], ldb=CDIM) + resid
    {
        const dim3 grd(CDIM / 128, THW / 128, BATCH);
        mma_gemm<1,3><<<grd, 256, 3 * ST1>>>(sch, nullptr, vph, nullptr, nullptr, qin,
                                             out, nullptr, nullptr,
                                             TF, TF, CDIM, CDIM,
                                             (long long)THW * TF,
                                             (long long)TF * CDIM,
                                             (long long)THW * CDIM,
                                             (long long)THW * CDIM);
    }
}

// round 15
// speedup vs baseline: 1.0098x; 1.0098x over previous
#include <cuda_runtime.h>
#include <cuda_fp16.h>
#include <math.h>
#include <stdint.h>

// Problem constants
#define BATCH 16
#define THW   2048
#define TF    2048
#define CDIM  512

#define NELEM_QK (BATCH * THW * CDIM)
#define NELEM_SC ((size_t)BATCH * THW * (size_t)TF)

// ---------------------------------------------------------------------------
// Scratch (device globals — no allocations allowed)
// ---------------------------------------------------------------------------
__device__ float g_sc [NELEM_SC];                 // fp32 scores
__device__ __half g_qh [NELEM_QK], g_ql [NELEM_QK];
__device__ __half g_kh [NELEM_QK], g_kl [NELEM_QK];
__device__ __half g_Wqh[CDIM*CDIM], g_Wql[CDIM*CDIM];
__device__ __half g_Wkh[CDIM*CDIM], g_Wkl[CDIM*CDIM];
__device__ __half g_Wvh[CDIM*CDIM], g_Wvl[CDIM*CDIM];
__device__ __half g_qinh[NELEM_QK], g_qinl[NELEM_QK]; // q-projection hi/lo (also residual)
__device__ __half g_kph [NELEM_QK], g_kpl [NELEM_QK]; // [b][t][c]
__device__ __half g_vph [NELEM_QK];                   // [b][t][c] hi only
__device__ __half g_sch [NELEM_SC];                   // fp16 attn (1-pass output)

// ---------------------------------------------------------------------------
// GEMM config: 128x128 tile, BK=32, 256 threads = 8 warps (2m x 4n),
// warp tile 64x32. 2 CTAs/SM (reg cap 128) + 2-stage cp.async pipeline
// (R12 champion config). NPASS: 3 = AhBh+AhBl+AlBh, 2 = AhBh+AlBh, 1 = AhBh.
// Fixed stage layout [Ah][Al][Bh][Bl] (unused sections idle for NPASS<3).
// B operand convention: B[k][n], row stride ldb (k-major).
// ---------------------------------------------------------------------------
#define BK 32
#define LDA_S 40                    // padded A row stride (halves)
#define LDB_S 136                   // padded B row stride (halves)
#define A_HB (128 * LDA_S * 2)      // 10240 bytes per A half-tile
#define B_HB (BK * LDB_S * 2)       // 8704 bytes per B half-tile
#define STAGE_B (2 * A_HB + 2 * B_HB)   // 37888
#define SMEM_GEMM (2 * STAGE_B)         // 75776 per CTA (x2 CTAs = 151552/SM)

__device__ __forceinline__ void ldsm4(uint32_t* r, uint32_t addr) {
    asm volatile("ldmatrix.sync.aligned.m8n8.x4.shared.b16 {%0,%1,%2,%3}, [%4];\n"
                 : "=r"(r[0]), "=r"(r[1]), "=r"(r[2]), "=r"(r[3]) : "r"(addr));
}
__device__ __forceinline__ void ldsm4t(uint32_t* r, uint32_t addr) {
    asm volatile("ldmatrix.sync.aligned.m8n8.x4.trans.shared.b16 {%0,%1,%2,%3}, [%4];\n"
                 : "=r"(r[0]), "=r"(r[1]), "=r"(r[2]), "=r"(r[3]) : "r"(addr));
}
__device__ __forceinline__ void mma16816(float* c, const uint32_t* a, const uint32_t* b) {
    asm volatile("mma.sync.aligned.m16n8k16.row.col.f32.f16.f16.f32 "
                 "{%0,%1,%2,%3},{%4,%5,%6,%7},{%8,%9},{%0,%1,%2,%3};\n"
                 : "+f"(c[0]), "+f"(c[1]), "+f"(c[2]), "+f"(c[3])
                 : "r"(a[0]), "r"(a[1]), "r"(a[2]), "r"(a[3]), "r"(b[0]), "r"(b[1]));
}
__device__ __forceinline__ void cp16(uint32_t dst, const void* src) {
    asm volatile("cp.async.cg.shared.global [%0], [%1], 16;\n" :: "r"(dst), "l"(src));
}
__device__ __forceinline__ void cp_commit() {
    asm volatile("cp.async.commit_group;\n" ::: "memory");
}
template <int N>
__device__ __forceinline__ void cp_wait() {
    asm volatile("cp.async.wait_group %0;\n" :: "n"(N) : "memory");
}

template <int NPASS>
__global__ __launch_bounds__(256, 2) void mma_gemm(
    const __half* __restrict__ Ahg, const __half* __restrict__ Alg,
    const __half* __restrict__ Bhg, const __half* __restrict__ Blg,
    const float* __restrict__ bias,
    const __half* __restrict__ residh, const __half* __restrict__ residl,
    float* __restrict__ Cf, __half* __restrict__ Ch, __half* __restrict__ Cl,
    int K, int lda, int ldb, int ldc,
    long long sA, long long sB, long long sC, long long sR)
{
    constexpr bool USE_AL = (NPASS >= 2);   // P3: Al*Bh
    constexpr bool USE_BL = (NPASS >= 3);   // P2: Ah*Bl

    extern __shared__ char smem[];
    const uint32_t smem_u32 = (uint32_t)__cvta_generic_to_shared(smem);

    const long long bz = blockIdx.z;
    Ahg += bz * sA; if (USE_AL) Alg += bz * sA;
    Bhg += bz * sB; if (USE_BL) Blg += bz * sB;
    if (Cf)     Cf     += bz * sC;
    if (Ch)     Ch     += bz * sC;
    if (Cl)     Cl     += bz * sC;
    if (residh) { residh += bz * sR; residl += bz * sR; }

    const int tid  = threadIdx.x;
    const int warp = tid >> 5;
    const int lane = tid & 31;
    const int wm = warp >> 2;
    const int wn = warp & 3;
    const int g   = lane >> 2;
    const int tig = lane & 3;

    const int row0 = blockIdx.y * 128;
    const int col0 = blockIdx.x * 128;

    // cp.async load maps: A half-tile 128x32 half = 64B/row, 2 threads/row
    const int ar  = tid >> 1;            // 0..127
    const int ab  = (tid & 1) * 32;      // byte offset {0,32}, +16 inner
    // B half-tile 32x128 half = 256B/row, 8 threads/row
    const int br  = tid >> 3;            // 0..31
    const int bb  = (tid & 7) * 32;      // byte offset, +16 inner

    // ldmatrix fragment address components (verified R4/R8)
    const int a_r = wm * 64 + (lane & 15);
    const int a_c = (lane >> 4) * 8;
    const int b_r = lane & 15;
    const int b_c = wn * 32 + ((lane & 16) ? 8 : 0);

    float acc[4][4][4];
    #pragma unroll
    for (int i = 0; i < 4; i++)
        #pragma unroll
        for (int j = 0; j < 4; j++)
            #pragma unroll
            for (int l = 0; l < 4; l++) acc[i][j][l] = 0.0f;

    const int NC = K / BK;

    const uint32_t OFF_AL = A_HB;
    const uint32_t OFF_BH = 2 * A_HB;
    const uint32_t OFF_BL = 2 * A_HB + B_HB;

    auto load_stage = [&](int stage, int chunk) {
        const uint32_t sb = smem_u32 + stage * STAGE_B;
        const int k0 = chunk * BK;
        #pragma unroll
        for (int i = 0; i < 2; i++) {
            const long long ao = (long long)(row0 + ar) * lda + k0 + (ab >> 1) + i * 8;
            const uint32_t ad = sb + ar * (LDA_S * 2) + ab + i * 16;
            cp16(ad, Ahg + ao);
            if (USE_AL) cp16(ad + OFF_AL, Alg + ao);
        }
        #pragma unroll
        for (int i = 0; i < 2; i++) {
            const long long bo = (long long)(k0 + br) * ldb + col0 + (bb >> 1) + i * 8;
            const uint32_t bd = sb + OFF_BH + br * (LDB_S * 2) + bb + i * 16;
            cp16(bd, Bhg + bo);
            if (USE_BL) cp16(bd + B_HB, Blg + bo);
        }
    };

    // prologue: chunk 0 -> stage 0
    load_stage(0, 0);
    cp_commit();

    for (int c = 0; c < NC; c++) {
        cp_wait<0>();       // chunk c resident
        __syncthreads();    // all warps past chunk c-1's buffer; chunk c visible

        if (c + 1 < NC) {   // fill the other stage; lands during compute of c
            load_stage((c + 1) & 1, c + 1);
            cp_commit();
        }

        const uint32_t sb  = smem_u32 + (c & 1) * STAGE_B;
        const uint32_t ah0 = sb;
        const uint32_t al0 = sb + OFF_AL;
        const uint32_t bh0 = sb + OFF_BH;
        const uint32_t bl0 = sb + OFF_BL;

        #pragma unroll
        for (int ks = 0; ks < 2; ks++) {
            uint32_t fah[4][4], fbh[4][2];
            #pragma unroll
            for (int mt = 0; mt < 4; mt++)
                ldsm4(fah[mt], ah0 + 2 * ((a_r + mt * 16) * LDA_S + a_c + ks * 16));
            {
                uint32_t t[4];
                ldsm4t(t, bh0 + 2 * ((ks * 16 + b_r) * LDB_S + b_c));
                fbh[0][0] = t[0]; fbh[0][1] = t[1]; fbh[1][0] = t[2]; fbh[1][1] = t[3];
                ldsm4t(t, bh0 + 2 * ((ks * 16 + b_r) * LDB_S + b_c + 16));
                fbh[2][0] = t[0]; fbh[2][1] = t[1]; fbh[3][0] = t[2]; fbh[3][1] = t[3];
            }
            // P1: Ah * Bh
            #pragma unroll
            for (int mt = 0; mt < 4; mt++)
                #pragma unroll
                for (int nt = 0; nt < 4; nt++)
                    mma16816(acc[mt][nt], fah[mt], fbh[nt]);

            // P2: Ah * Bl (scoped fragments — keep reg count low)
            if (USE_BL) {
                uint32_t fbl[4][2];
                uint32_t t[4];
                ldsm4t(t, bl0 + 2 * ((ks * 16 + b_r) * LDB_S + b_c));
                fbl[0][0] = t[0]; fbl[0][1] = t[1]; fbl[1][0] = t[2]; fbl[1][1] = t[3];
                ldsm4t(t, bl0 + 2 * ((ks * 16 + b_r) * LDB_S + b_c + 16));
                fbl[2][0] = t[0]; fbl[2][1] = t[1]; fbl[3][0] = t[2]; fbl[3][1] = t[3];
                #pragma unroll
                for (int mt = 0; mt < 4; mt++)
                    #pragma unroll
                    for (int nt = 0; nt < 4; nt++)
                        mma16816(acc[mt][nt], fah[mt], fbl[nt]);
            }
            // P3: Al * Bh (one A-fragment at a time)
            if (USE_AL) {
                uint32_t fal[4];
                #pragma unroll
                for (int mt = 0; mt < 4; mt++) {
                    ldsm4(fal, al0 + 2 * ((a_r + mt * 16) * LDA_S + a_c + ks * 16));
                    #pragma unroll
                    for (int nt = 0; nt < 4; nt++)
                        mma16816(acc[mt][nt], fal, fbh[nt]);
                }
            }
        }
    }

    // ---- epilogue (mapping verified R4/R8) ----
    #pragma unroll
    for (int mt = 0; mt < 4; mt++) {
        #pragma unroll
        for (int nt = 0; nt < 4; nt++) {
            const int r = row0 + wm * 64 + mt * 16 + g;
            const int c = col0 + wn * 32 + nt * 8 + 2 * tig;
            float2 v0 = make_float2(acc[mt][nt][0], acc[mt][nt][1]);
            float2 v1 = make_float2(acc[mt][nt][2], acc[mt][nt][3]);
            if (bias) {
                const float b0 = bias[c], b1 = bias[c + 1];
                v0.x += b0; v0.y += b1;
                v1.x += b0; v1.y += b1;
            }
            if (residh) {
                // residual = hi + lo fp16 reconstruction (~2^-22 rel of fp32 value)
                const __half2 h0 = *reinterpret_cast<const __half2*>(&residh[(long long)r * ldc + c]);
                const __half2 l0 = *reinterpret_cast<const __half2*>(&residl[(long long)r * ldc + c]);
                const __half2 h1 = *reinterpret_cast<const __half2*>(&residh[(long long)(r + 8) * ldc + c]);
                const __half2 l1 = *reinterpret_cast<const __half2*>(&residl[(long long)(r + 8) * ldc + c]);
                v0.x += __half2float(__low2half(h0))  + __half2float(__low2half(l0));
                v0.y += __half2float(__high2half(h0)) + __half2float(__high2half(l0));
                v1.x += __half2float(__low2half(h1))  + __half2float(__low2half(l1));
                v1.y += __half2float(__high2half(h1)) + __half2float(__high2half(l1));
            }
            if (Cf) {
                *reinterpret_cast<float2*>(&Cf[(long long)r * ldc + c]) = v0;
                *reinterpret_cast<float2*>(&Cf[(long long)(r + 8) * ldc + c]) = v1;
            }
            if (Ch) {
                const __half h0 = __float2half_rn(v0.x);
                const __half h1 = __float2half_rn(v0.y);
                const __half h2 = __float2half_rn(v1.x);
                const __half h3 = __float2half_rn(v1.y);
                *reinterpret_cast<__half2*>(&Ch[(long long)r * ldc + c]) =
                    __halves2half2(h0, h1);
                *reinterpret_cast<__half2*>(&Ch[(long long)(r + 8) * ldc + c]) =
                    __halves2half2(h2, h3);
                if (Cl) {
                    *reinterpret_cast<__half2*>(&Cl[(long long)r * ldc + c]) =
                        __halves2half2(__float2half_rn(v0.x - __half2float(h0)),
                                       __float2half_rn(v0.y - __half2float(h1)));
                    *reinterpret_cast<__half2*>(&Cl[(long long)(r + 8) * ldc + c]) =
                        __halves2half2(__float2half_rn(v1.x - __half2float(h2)),
                                       __float2half_rn(v1.y - __half2float(h3)));
                }
            }
        }
    }
}

// ---------------------------------------------------------------------------
// Fused fp32 -> fp16 hi/lo splits: blockIdx.y selects among NSRC sources
// ---------------------------------------------------------------------------
__global__ __launch_bounds__(256) void split2_kernel(
    const float* __restrict__ x0, __half* __restrict__ h0o, __half* __restrict__ l0o,
    const float* __restrict__ x1, __half* __restrict__ h1o, __half* __restrict__ l1o,
    int n4)
{
    const int idx = blockIdx.x * 256 + threadIdx.x;
    if (idx >= n4) return;
    const float* x = blockIdx.y ? x1 : x0;
    __half* h = blockIdx.y ? h1o : h0o;
    __half* l = blockIdx.y ? l1o : l0o;
    const float4 v = reinterpret_cast<const float4*>(x)[idx];
    const __half a0 = __float2half_rn(v.x), a1 = __float2half_rn(v.y);
    const __half a2 = __float2half_rn(v.z), a3 = __float2half_rn(v.w);
    reinterpret_cast<__half2*>(h)[idx * 2]     = __halves2half2(a0, a1);
    reinterpret_cast<__half2*>(h)[idx * 2 + 1] = __halves2half2(a2, a3);
    reinterpret_cast<__half2*>(l)[idx * 2] = __halves2half2(
        __float2half_rn(v.x - __half2float(a0)),
        __float2half_rn(v.y - __half2float(a1)));
    reinterpret_cast<__half2*>(l)[idx * 2 + 1] = __halves2half2(
        __float2half_rn(v.z - __half2float(a2)),
        __float2half_rn(v.w - __half2float(a3)));
}

__global__ __launch_bounds__(256) void split3_kernel(
    const float* __restrict__ x0, __half* __restrict__ h0o, __half* __restrict__ l0o,
    const float* __restrict__ x1, __half* __restrict__ h1o, __half* __restrict__ l1o,
    const float* __restrict__ x2, __half* __restrict__ h2o, __half* __restrict__ l2o,
    int n4)
{
    const int idx = blockIdx.x * 256 + threadIdx.x;
    if (idx >= n4) return;
    const float* x = (blockIdx.y == 0) ? x0 : (blockIdx.y == 1) ? x1 : x2;
    __half* h = (blockIdx.y == 0) ? h0o : (blockIdx.y == 1) ? h1o : h2o;
    __half* l = (blockIdx.y == 0) ? l0o : (blockIdx.y == 1) ? l1o : l2o;
    const float4 v = reinterpret_cast<const float4*>(x)[idx];
    const __half a0 = __float2half_rn(v.x), a1 = __float2half_rn(v.y);
    const __half a2 = __float2half_rn(v.z), a3 = __float2half_rn(v.w);
    reinterpret_cast<__half2*>(h)[idx * 2]     = __halves2half2(a0, a1);
    reinterpret_cast<__half2*>(h)[idx * 2 + 1] = __halves2half2(a2, a3);
    reinterpret_cast<__half2*>(l)[idx * 2] = __halves2half2(
        __float2half_rn(v.x - __half2float(a0)),
        __float2half_rn(v.y - __half2float(a1)));
    reinterpret_cast<__half2*>(l)[idx * 2 + 1] = __halves2half2(
        __float2half_rn(v.z - __half2float(a2)),
        __float2half_rn(v.w - __half2float(a3)));
}

// ---------------------------------------------------------------------------
// Row softmax over TF, fp16 output (output GEMM is 1-pass)
// ---------------------------------------------------------------------------
__global__ __launch_bounds__(256) void softmax_h(
    const float* __restrict__ S, __half* __restrict__ H)
{
    const long long row = blockIdx.x;
    const float* p = S + row * (long long)TF;
    const int tid = threadIdx.x;
    __shared__ float red[32];

    float4 v0 = *reinterpret_cast<const float4*>(&p[tid * 8]);
    float4 v1 = *reinterpret_cast<const float4*>(&p[tid * 8 + 4]);

    float lmax = fmaxf(fmaxf(fmaxf(v0.x, v0.y), fmaxf(v0.z, v0.w)),
                       fmaxf(fmaxf(v1.x, v1.y), fmaxf(v1.z, v1.w)));
    #pragma unroll
    for (int o = 16; o; o >>= 1) lmax = fmaxf(lmax, __shfl_xor_sync(0xffffffffu, lmax, o));
    if ((tid & 31) == 0) red[tid >> 5] = lmax;
    __syncthreads();
    if (tid < 32) {
        float v = (tid < 8) ? red[tid] : -INFINITY;
        #pragma unroll
        for (int o = 4; o; o >>= 1) v = fmaxf(v, __shfl_xor_sync(0xffffffffu, v, o));
        if (tid == 0) red[0] = v;
    }
    __syncthreads();
    const float mx = red[0];
    __syncthreads();

    v0.x = __expf(v0.x - mx); v0.y = __expf(v0.y - mx);
    v0.z = __expf(v0.z - mx); v0.w = __expf(v0.w - mx);
    v1.x = __expf(v1.x - mx); v1.y = __expf(v1.y - mx);
    v1.z = __expf(v1.z - mx); v1.w = __expf(v1.w - mx);
    float lsum = (v0.x + v0.y + v0.z + v0.w) + (v1.x + v1.y + v1.z + v1.w);
    #pragma unroll
    for (int o = 16; o; o >>= 1) lsum += __shfl_xor_sync(0xffffffffu, lsum, o);
    if ((tid & 31) == 0) red[tid >> 5] = lsum;
    __syncthreads();
    if (tid < 32) {
        float v = (tid < 8) ? red[tid] : 0.0f;
        #pragma unroll
        for (int o = 4; o; o >>= 1) v += __shfl_xor_sync(0xffffffffu, v, o);
        if (tid == 0) red[0] = v;
    }
    __syncthreads();
    const float inv = 1.0f / red[0];

    __half* hp = H + row * (long long)TF + tid * 8;
    *reinterpret_cast<__half2*>(hp)     = __halves2half2(__float2half_rn(v0.x * inv), __float2half_rn(v0.y * inv));
    *reinterpret_cast<__half2*>(hp + 2) = __halves2half2(__float2half_rn(v0.z * inv), __float2half_rn(v0.w * inv));
    *reinterpret_cast<__half2*>(hp + 4) = __halves2half2(__float2half_rn(v1.x * inv), __float2half_rn(v1.y * inv));
    *reinterpret_cast<__half2*>(hp + 6) = __halves2half2(__float2half_rn(v1.z * inv), __float2half_rn(v1.w * inv));
}

// ---------------------------------------------------------------------------
// kernel_launch
// ---------------------------------------------------------------------------
extern "C" void kernel_launch(void* const* d_in, const int* in_sizes, int n_in,
                              void* d_out, int out_size)
{
    const float* q  = (const float*)d_in[0];
    const float* k  = (const float*)d_in[1];
    const float* Wq = (const float*)d_in[2];
    const float* bq = (const float*)d_in[3];
    const float* Wk = (const float*)d_in[4];
    const float* bk = (const float*)d_in[5];
    const float* Wv = (const float*)d_in[6];
    const float* bv = (const float*)d_in[7];
    float* out = (float*)d_out;

    void* p;
    cudaGetSymbolAddress(&p, g_sc);   float* sc  = (float*)p;
    cudaGetSymbolAddress(&p, g_qh);   __half* qh = (__half*)p;
    cudaGetSymbolAddress(&p, g_ql);   __half* ql = (__half*)p;
    cudaGetSymbolAddress(&p, g_kh);   __half* kh = (__half*)p;
    cudaGetSymbolAddress(&p, g_kl);   __half* kl = (__half*)p;
    cudaGetSymbolAddress(&p, g_Wqh);  __half* Wqh = (__half*)p;
    cudaGetSymbolAddress(&p, g_Wql);  __half* Wql = (__half*)p;
    cudaGetSymbolAddress(&p, g_Wkh);  __half* Wkh = (__half*)p;
    cudaGetSymbolAddress(&p, g_Wkl);  __half* Wkl = (__half*)p;
    cudaGetSymbolAddress(&p, g_Wvh);  __half* Wvh = (__half*)p;
    cudaGetSymbolAddress(&p, g_Wvl);  __half* Wvl = (__half*)p;
    cudaGetSymbolAddress(&p, g_qinh); __half* qinh = (__half*)p;
    cudaGetSymbolAddress(&p, g_qinl); __half* qinl = (__half*)p;
    cudaGetSymbolAddress(&p, g_kph);  __half* kph  = (__half*)p;
    cudaGetSymbolAddress(&p, g_kpl);  __half* kpl  = (__half*)p;
    cudaGetSymbolAddress(&p, g_vph);  __half* vph  = (__half*)p;
    cudaGetSymbolAddress(&p, g_sch);  __half* sch  = (__half*)p;

    cudaFuncSetAttribute(mma_gemm<3>, cudaFuncAttributeMaxDynamicSharedMemorySize, SMEM_GEMM);
    cudaFuncSetAttribute(mma_gemm<2>, cudaFuncAttributeMaxDynamicSharedMemorySize, SMEM_GEMM);
    cudaFuncSetAttribute(mma_gemm<1>, cudaFuncAttributeMaxDynamicSharedMemorySize, SMEM_GEMM);

    // 1. split inputs + weights to fp16 hi/lo (fused launches)
    {
        const int n4 = NELEM_QK / 4;
        split2_kernel<<<dim3(n4 / 256, 2), 256>>>(q, qh, ql, k, kh, kl, n4);
        const int w4 = CDIM * CDIM / 4;
        split3_kernel<<<dim3(w4 / 256, 3), 256>>>(Wq, Wqh, Wql,
                                                  Wk, Wkh, Wkl,
                                                  Wv, Wvh, Wvl, w4);
    }
    // 2. projections: q,k 3-pass; v 2-pass  (B = W[k][n], ldb = CDIM)
    {
        const dim3 grd(CDIM / 128, (BATCH * THW) / 128, 1);
        mma_gemm<3><<<grd, 256, SMEM_GEMM>>>(qh, ql, Wqh, Wql, bq, nullptr, nullptr,
                                             nullptr, qinh, qinl,
                                             CDIM, CDIM, CDIM, CDIM, 0, 0, 0, 0);
        mma_gemm<3><<<grd, 256, SMEM_GEMM>>>(kh, kl, Wkh, Wkl, bk, nullptr, nullptr,
                                             nullptr, kph, kpl,
                                             CDIM, CDIM, CDIM, CDIM, 0, 0, 0, 0);
        mma_gemm<2><<<grd, 256, SMEM_GEMM>>>(kh, kl, Wvh, nullptr, bv, nullptr, nullptr,
                                             nullptr, vph, nullptr,
                                             CDIM, CDIM, CDIM, CDIM, 0, 0, 0, 0);
    }
    // 3. scores (3-pass): qin (lda=CDIM) x raw-view kin[c][t] (B[k=c][n=t], ldb=TF)
    {
        const dim3 grd(TF / 128, THW / 128, BATCH);
        mma_gemm<3><<<grd, 256, SMEM_GEMM>>>(qinh, qinl, kph, kpl, nullptr, nullptr, nullptr,
                                             sc, nullptr, nullptr,
                                             CDIM, CDIM, TF, TF,
                                             (long long)THW * CDIM,
                                             (long long)TF * CDIM,
                                             (long long)THW * TF, 0);
    }
    // 4. softmax -> fp16
    softmax_h<<<BATCH * THW, 256>>>(sc, sch);
    // 5. output (1-pass fp16): attn (lda=TF) x vp[t][c] (B[k=t][n=c], ldb=CDIM)
    //    + residual reconstructed from qinh+qinl
    {
        const dim3 grd(CDIM / 128, THW / 128, BATCH);
        mma_gemm<1><<<grd, 256, SMEM_GEMM>>>(sch, nullptr, vph, nullptr, nullptr,
                                             qinh, qinl,
                                             out, nullptr, nullptr,
                                             TF, TF, CDIM, CDIM,
                                             (long long)THW * TF,
                                             (long long)TF * CDIM,
                                             (long long)THW * CDIM,
                                             (long long)THW * CDIM);
    }
}

// round 17
// speedup vs baseline: 1.0157x; 1.0058x over previous
#include <cuda_runtime.h>
#include <cuda_fp16.h>
#include <math.h>
#include <stdint.h>

// Problem constants
#define BATCH 16
#define THW   2048
#define TF    2048
#define CDIM  512

#define NELEM_QK (BATCH * THW * CDIM)
#define NELEM_SC ((size_t)BATCH * THW * (size_t)TF)

// ---------------------------------------------------------------------------
// Scratch (device globals — no allocations allowed)
// ---------------------------------------------------------------------------
__device__ float g_sc [NELEM_SC];                 // fp32 scores
__device__ __half g_qh [NELEM_QK], g_ql [NELEM_QK];
__device__ __half g_kh [NELEM_QK], g_kl [NELEM_QK];
__device__ __half g_Wqh[CDIM*CDIM], g_Wql[CDIM*CDIM];
__device__ __half g_Wkh[CDIM*CDIM], g_Wkl[CDIM*CDIM];
__device__ __half g_Wvh[CDIM*CDIM], g_Wvl[CDIM*CDIM];
__device__ __half g_qinh[NELEM_QK], g_qinl[NELEM_QK]; // q-projection hi/lo (also residual)
__device__ __half g_kph [NELEM_QK], g_kpl [NELEM_QK]; // [b][t][c]
__device__ __half g_vph [NELEM_QK];                   // [b][t][c] hi only
__device__ __half g_sch [NELEM_SC];                   // fp16 attn (1-pass output)

// ---------------------------------------------------------------------------
// GEMM config: 128x128 tile, BK=32, 256 threads = 8 warps (2m x 4n),
// warp tile 64x32. 2 CTAs/SM (reg cap 128) + 2-stage cp.async pipeline
// (R12/R15 champion config). Fixed stage layout [Ah][Al][Bh][Bl].
// B operand convention: B[k][n], row stride ldb (k-major).
// ---------------------------------------------------------------------------
#define BK 32
#define LDA_S 40                    // padded A row stride (halves)
#define LDB_S 136                   // padded B row stride (halves)
#define A_HB (128 * LDA_S * 2)      // 10240 bytes per A half-tile
#define B_HB (BK * LDB_S * 2)       // 8704 bytes per B half-tile
#define STAGE_B (2 * A_HB + 2 * B_HB)   // 37888
#define SMEM_GEMM (2 * STAGE_B)         // 75776 per CTA (x2 CTAs = 151552/SM)

__device__ __forceinline__ void ldsm4(uint32_t* r, uint32_t addr) {
    asm volatile("ldmatrix.sync.aligned.m8n8.x4.shared.b16 {%0,%1,%2,%3}, [%4];\n"
                 : "=r"(r[0]), "=r"(r[1]), "=r"(r[2]), "=r"(r[3]) : "r"(addr));
}
__device__ __forceinline__ void ldsm4t(uint32_t* r, uint32_t addr) {
    asm volatile("ldmatrix.sync.aligned.m8n8.x4.trans.shared.b16 {%0,%1,%2,%3}, [%4];\n"
                 : "=r"(r[0]), "=r"(r[1]), "=r"(r[2]), "=r"(r[3]) : "r"(addr));
}
__device__ __forceinline__ void mma16816(float* c, const uint32_t* a, const uint32_t* b) {
    asm volatile("mma.sync.aligned.m16n8k16.row.col.f32.f16.f16.f32 "
                 "{%0,%1,%2,%3},{%4,%5,%6,%7},{%8,%9},{%0,%1,%2,%3};\n"
                 : "+f"(c[0]), "+f"(c[1]), "+f"(c[2]), "+f"(c[3])
                 : "r"(a[0]), "r"(a[1]), "r"(a[2]), "r"(a[3]), "r"(b[0]), "r"(b[1]));
}
__device__ __forceinline__ void cp16(uint32_t dst, const void* src) {
    asm volatile("cp.async.cg.shared.global [%0], [%1], 16;\n" :: "r"(dst), "l"(src));
}
__device__ __forceinline__ void cp_commit() {
    asm volatile("cp.async.commit_group;\n" ::: "memory");
}
template <int N>
__device__ __forceinline__ void cp_wait() {
    asm volatile("cp.async.wait_group %0;\n" :: "n"(N) : "memory");
}

// ---------------------------------------------------------------------------
// Generic GEMM (scores NPASS=3, output NPASS=1) — champion code, unchanged.
// ---------------------------------------------------------------------------
template <int NPASS>
__global__ __launch_bounds__(256, 2) void mma_gemm(
    const __half* __restrict__ Ahg, const __half* __restrict__ Alg,
    const __half* __restrict__ Bhg, const __half* __restrict__ Blg,
    const float* __restrict__ bias,
    const __half* __restrict__ residh, const __half* __restrict__ residl,
    float* __restrict__ Cf, __half* __restrict__ Ch, __half* __restrict__ Cl,
    int K, int lda, int ldb, int ldc,
    long long sA, long long sB, long long sC, long long sR)
{
    constexpr bool USE_AL = (NPASS >= 2);
    constexpr bool USE_BL = (NPASS >= 3);

    extern __shared__ char smem[];
    const uint32_t smem_u32 = (uint32_t)__cvta_generic_to_shared(smem);

    const long long bz = blockIdx.z;
    Ahg += bz * sA; if (USE_AL) Alg += bz * sA;
    Bhg += bz * sB; if (USE_BL) Blg += bz * sB;
    if (Cf)     Cf     += bz * sC;
    if (Ch)     Ch     += bz * sC;
    if (Cl)     Cl     += bz * sC;
    if (residh) { residh += bz * sR; residl += bz * sR; }

    const int tid  = threadIdx.x;
    const int warp = tid >> 5;
    const int lane = tid & 31;
    const int wm = warp >> 2;
    const int wn = warp & 3;
    const int g   = lane >> 2;
    const int tig = lane & 3;

    const int row0 = blockIdx.y * 128;
    const int col0 = blockIdx.x * 128;

    const int ar  = tid >> 1;
    const int ab  = (tid & 1) * 32;
    const int br  = tid >> 3;
    const int bb  = (tid & 7) * 32;

    const int a_r = wm * 64 + (lane & 15);
    const int a_c = (lane >> 4) * 8;
    const int b_r = lane & 15;
    const int b_c = wn * 32 + ((lane & 16) ? 8 : 0);

    float acc[4][4][4];
    #pragma unroll
    for (int i = 0; i < 4; i++)
        #pragma unroll
        for (int j = 0; j < 4; j++)
            #pragma unroll
            for (int l = 0; l < 4; l++) acc[i][j][l] = 0.0f;

    const int NC = K / BK;

    const uint32_t OFF_AL = A_HB;
    const uint32_t OFF_BH = 2 * A_HB;
    const uint32_t OFF_BL = 2 * A_HB + B_HB;

    auto load_stage = [&](int stage, int chunk) {
        const uint32_t sb = smem_u32 + stage * STAGE_B;
        const int k0 = chunk * BK;
        #pragma unroll
        for (int i = 0; i < 2; i++) {
            const long long ao = (long long)(row0 + ar) * lda + k0 + (ab >> 1) + i * 8;
            const uint32_t ad = sb + ar * (LDA_S * 2) + ab + i * 16;
            cp16(ad, Ahg + ao);
            if (USE_AL) cp16(ad + OFF_AL, Alg + ao);
        }
        #pragma unroll
        for (int i = 0; i < 2; i++) {
            const long long bo = (long long)(k0 + br) * ldb + col0 + (bb >> 1) + i * 8;
            const uint32_t bd = sb + OFF_BH + br * (LDB_S * 2) + bb + i * 16;
            cp16(bd, Bhg + bo);
            if (USE_BL) cp16(bd + B_HB, Blg + bo);
        }
    };

    load_stage(0, 0);
    cp_commit();

    for (int c = 0; c < NC; c++) {
        cp_wait<0>();
        __syncthreads();

        if (c + 1 < NC) {
            load_stage((c + 1) & 1, c + 1);
            cp_commit();
        }

        const uint32_t sb  = smem_u32 + (c & 1) * STAGE_B;
        const uint32_t ah0 = sb;
        const uint32_t al0 = sb + OFF_AL;
        const uint32_t bh0 = sb + OFF_BH;
        const uint32_t bl0 = sb + OFF_BL;

        #pragma unroll
        for (int ks = 0; ks < 2; ks++) {
            uint32_t fah[4][4], fbh[4][2];
            #pragma unroll
            for (int mt = 0; mt < 4; mt++)
                ldsm4(fah[mt], ah0 + 2 * ((a_r + mt * 16) * LDA_S + a_c + ks * 16));
            {
                uint32_t t[4];
                ldsm4t(t, bh0 + 2 * ((ks * 16 + b_r) * LDB_S + b_c));
                fbh[0][0] = t[0]; fbh[0][1] = t[1]; fbh[1][0] = t[2]; fbh[1][1] = t[3];
                ldsm4t(t, bh0 + 2 * ((ks * 16 + b_r) * LDB_S + b_c + 16));
                fbh[2][0] = t[0]; fbh[2][1] = t[1]; fbh[3][0] = t[2]; fbh[3][1] = t[3];
            }
            #pragma unroll
            for (int mt = 0; mt < 4; mt++)
                #pragma unroll
                for (int nt = 0; nt < 4; nt++)
                    mma16816(acc[mt][nt], fah[mt], fbh[nt]);

            if (USE_BL) {
                uint32_t fbl[4][2];
                uint32_t t[4];
                ldsm4t(t, bl0 + 2 * ((ks * 16 + b_r) * LDB_S + b_c));
                fbl[0][0] = t[0]; fbl[0][1] = t[1]; fbl[1][0] = t[2]; fbl[1][1] = t[3];
                ldsm4t(t, bl0 + 2 * ((ks * 16 + b_r) * LDB_S + b_c + 16));
                fbl[2][0] = t[0]; fbl[2][1] = t[1]; fbl[3][0] = t[2]; fbl[3][1] = t[3];
                #pragma unroll
                for (int mt = 0; mt < 4; mt++)
                    #pragma unroll
                    for (int nt = 0; nt < 4; nt++)
                        mma16816(acc[mt][nt], fah[mt], fbl[nt]);
            }
            if (USE_AL) {
                uint32_t fal[4];
                #pragma unroll
                for (int mt = 0; mt < 4; mt++) {
                    ldsm4(fal, al0 + 2 * ((a_r + mt * 16) * LDA_S + a_c + ks * 16));
                    #pragma unroll
                    for (int nt = 0; nt < 4; nt++)
                        mma16816(acc[mt][nt], fal, fbh[nt]);
                }
            }
        }
    }

    #pragma unroll
    for (int mt = 0; mt < 4; mt++) {
        #pragma unroll
        for (int nt = 0; nt < 4; nt++) {
            const int r = row0 + wm * 64 + mt * 16 + g;
            const int c = col0 + wn * 32 + nt * 8 + 2 * tig;
            float2 v0 = make_float2(acc[mt][nt][0], acc[mt][nt][1]);
            float2 v1 = make_float2(acc[mt][nt][2], acc[mt][nt][3]);
            if (bias) {
                const float b0 = bias[c], b1 = bias[c + 1];
                v0.x += b0; v0.y += b1;
                v1.x += b0; v1.y += b1;
            }
            if (residh) {
                const __half2 h0 = *reinterpret_cast<const __half2*>(&residh[(long long)r * ldc + c]);
                const __half2 l0 = *reinterpret_cast<const __half2*>(&residl[(long long)r * ldc + c]);
                const __half2 h1 = *reinterpret_cast<const __half2*>(&residh[(long long)(r + 8) * ldc + c]);
                const __half2 l1 = *reinterpret_cast<const __half2*>(&residl[(long long)(r + 8) * ldc + c]);
                v0.x += __half2float(__low2half(h0))  + __half2float(__low2half(l0));
                v0.y += __half2float(__high2half(h0)) + __half2float(__high2half(l0));
                v1.x += __half2float(__low2half(h1))  + __half2float(__low2half(l1));
                v1.y += __half2float(__high2half(h1)) + __half2float(__high2half(l1));
            }
            if (Cf) {
                *reinterpret_cast<float2*>(&Cf[(long long)r * ldc + c]) = v0;
                *reinterpret_cast<float2*>(&Cf[(long long)(r + 8) * ldc + c]) = v1;
            }
            if (Ch) {
                const __half h0 = __float2half_rn(v0.x);
                const __half h1 = __float2half_rn(v0.y);
                const __half h2 = __float2half_rn(v1.x);
                const __half h3 = __float2half_rn(v1.y);
                *reinterpret_cast<__half2*>(&Ch[(long long)r * ldc + c]) =
                    __halves2half2(h0, h1);
                *reinterpret_cast<__half2*>(&Ch[(long long)(r + 8) * ldc + c]) =
                    __halves2half2(h2, h3);
                if (Cl) {
                    *reinterpret_cast<__half2*>(&Cl[(long long)r * ldc + c]) =
                        __halves2half2(__float2half_rn(v0.x - __half2float(h0)),
                                       __float2half_rn(v0.y - __half2float(h1)));
                    *reinterpret_cast<__half2*>(&Cl[(long long)(r + 8) * ldc + c]) =
                        __halves2half2(__float2half_rn(v1.x - __half2float(h2)),
                                       __float2half_rn(v1.y - __half2float(h3)));
                }
            }
        }
    }
}

// ---------------------------------------------------------------------------
// Merged projection kernel: blockIdx.z in {0,1,2} = {q-proj, k-proj, v-proj}.
// Same mainloop as mma_gemm<3> with runtime uniform use_bl (v drops Ah*Bl).
// K = lda = ldb = ldc = CDIM for all three.
// ---------------------------------------------------------------------------
__global__ __launch_bounds__(256, 2) void proj_gemm(
    const __half* __restrict__ qh, const __half* __restrict__ ql,
    const __half* __restrict__ kh, const __half* __restrict__ kl,
    const __half* __restrict__ Wqh, const __half* __restrict__ Wql,
    const __half* __restrict__ Wkh, const __half* __restrict__ Wkl,
    const __half* __restrict__ Wvh,
    const float* __restrict__ bq, const float* __restrict__ bk,
    const float* __restrict__ bv,
    __half* __restrict__ qinh, __half* __restrict__ qinl,
    __half* __restrict__ kph, __half* __restrict__ kpl,
    __half* __restrict__ vph)
{
    const int z = blockIdx.z;
    const __half* Ahg = (z == 0) ? qh : kh;
    const __half* Alg = (z == 0) ? ql : kl;
    const __half* Bhg = (z == 0) ? Wqh : (z == 1) ? Wkh : Wvh;
    const __half* Blg = (z == 0) ? Wql : Wkl;      // unused when z==2
    const float*  bias = (z == 0) ? bq : (z == 1) ? bk : bv;
    __half* Ch = (z == 0) ? qinh : (z == 1) ? kph : vph;
    __half* Cl = (z == 0) ? qinl : (z == 1) ? kpl : nullptr;
    const bool use_bl = (z < 2);

    extern __shared__ char smem[];
    const uint32_t smem_u32 = (uint32_t)__cvta_generic_to_shared(smem);

    const int tid  = threadIdx.x;
    const int warp = tid >> 5;
    const int lane = tid & 31;
    const int wm = warp >> 2;
    const int wn = warp & 3;
    const int g   = lane >> 2;
    const int tig = lane & 3;

    const int row0 = blockIdx.y * 128;
    const int col0 = blockIdx.x * 128;

    const int ar  = tid >> 1;
    const int ab  = (tid & 1) * 32;
    const int br  = tid >> 3;
    const int bb  = (tid & 7) * 32;

    const int a_r = wm * 64 + (lane & 15);
    const int a_c = (lane >> 4) * 8;
    const int b_r = lane & 15;
    const int b_c = wn * 32 + ((lane & 16) ? 8 : 0);

    float acc[4][4][4];
    #pragma unroll
    for (int i = 0; i < 4; i++)
        #pragma unroll
        for (int j = 0; j < 4; j++)
            #pragma unroll
            for (int l = 0; l < 4; l++) acc[i][j][l] = 0.0f;

    const int NC = CDIM / BK;   // 16

    const uint32_t OFF_AL = A_HB;
    const uint32_t OFF_BH = 2 * A_HB;
    const uint32_t OFF_BL = 2 * A_HB + B_HB;

    auto load_stage = [&](int stage, int chunk) {
        const uint32_t sb = smem_u32 + stage * STAGE_B;
        const int k0 = chunk * BK;
        #pragma unroll
        for (int i = 0; i < 2; i++) {
            const long long ao = (long long)(row0 + ar) * CDIM + k0 + (ab >> 1) + i * 8;
            const uint32_t ad = sb + ar * (LDA_S * 2) + ab + i * 16;
            cp16(ad, Ahg + ao);
            cp16(ad + OFF_AL, Alg + ao);
        }
        #pragma unroll
        for (int i = 0; i < 2; i++) {
            const long long bo = (long long)(k0 + br) * CDIM + col0 + (bb >> 1) + i * 8;
            const uint32_t bd = sb + OFF_BH + br * (LDB_S * 2) + bb + i * 16;
            cp16(bd, Bhg + bo);
            if (use_bl) cp16(bd + B_HB, Blg + bo);
        }
    };

    load_stage(0, 0);
    cp_commit();

    for (int c = 0; c < NC; c++) {
        cp_wait<0>();
        __syncthreads();

        if (c + 1 < NC) {
            load_stage((c + 1) & 1, c + 1);
            cp_commit();
        }

        const uint32_t sb  = smem_u32 + (c & 1) * STAGE_B;
        const uint32_t ah0 = sb;
        const uint32_t al0 = sb + OFF_AL;
        const uint32_t bh0 = sb + OFF_BH;
        const uint32_t bl0 = sb + OFF_BL;

        #pragma unroll
        for (int ks = 0; ks < 2; ks++) {
            uint32_t fah[4][4], fbh[4][2];
            #pragma unroll
            for (int mt = 0; mt < 4; mt++)
                ldsm4(fah[mt], ah0 + 2 * ((a_r + mt * 16) * LDA_S + a_c + ks * 16));
            {
                uint32_t t[4];
                ldsm4t(t, bh0 + 2 * ((ks * 16 + b_r) * LDB_S + b_c));
                fbh[0][0] = t[0]; fbh[0][1] = t[1]; fbh[1][0] = t[2]; fbh[1][1] = t[3];
                ldsm4t(t, bh0 + 2 * ((ks * 16 + b_r) * LDB_S + b_c + 16));
                fbh[2][0] = t[0]; fbh[2][1] = t[1]; fbh[3][0] = t[2]; fbh[3][1] = t[3];
            }
            // P1: Ah * Bh
            #pragma unroll
            for (int mt = 0; mt < 4; mt++)
                #pragma unroll
                for (int nt = 0; nt < 4; nt++)
                    mma16816(acc[mt][nt], fah[mt], fbh[nt]);

            // P2: Ah * Bl (runtime-uniform; skipped for v-projection)
            if (use_bl) {
                uint32_t fbl[4][2];
                uint32_t t[4];
                ldsm4t(t, bl0 + 2 * ((ks * 16 + b_r) * LDB_S + b_c));
                fbl[0][0] = t[0]; fbl[0][1] = t[1]; fbl[1][0] = t[2]; fbl[1][1] = t[3];
                ldsm4t(t, bl0 + 2 * ((ks * 16 + b_r) * LDB_S + b_c + 16));
                fbl[2][0] = t[0]; fbl[2][1] = t[1]; fbl[3][0] = t[2]; fbl[3][1] = t[3];
                #pragma unroll
                for (int mt = 0; mt < 4; mt++)
                    #pragma unroll
                    for (int nt = 0; nt < 4; nt++)
                        mma16816(acc[mt][nt], fah[mt], fbl[nt]);
            }
            // P3: Al * Bh (always)
            {
                uint32_t fal[4];
                #pragma unroll
                for (int mt = 0; mt < 4; mt++) {
                    ldsm4(fal, al0 + 2 * ((a_r + mt * 16) * LDA_S + a_c + ks * 16));
                    #pragma unroll
                    for (int nt = 0; nt < 4; nt++)
                        mma16816(acc[mt][nt], fal, fbh[nt]);
                }
            }
        }
    }

    // epilogue: bias + fp16 hi(/lo) outputs
    #pragma unroll
    for (int mt = 0; mt < 4; mt++) {
        #pragma unroll
        for (int nt = 0; nt < 4; nt++) {
            const int r = row0 + wm * 64 + mt * 16 + g;
            const int c = col0 + wn * 32 + nt * 8 + 2 * tig;
            float2 v0 = make_float2(acc[mt][nt][0], acc[mt][nt][1]);
            float2 v1 = make_float2(acc[mt][nt][2], acc[mt][nt][3]);
            const float b0 = bias[c], b1 = bias[c + 1];
            v0.x += b0; v0.y += b1;
            v1.x += b0; v1.y += b1;
            const __half h0 = __float2half_rn(v0.x);
            const __half h1 = __float2half_rn(v0.y);
            const __half h2 = __float2half_rn(v1.x);
            const __half h3 = __float2half_rn(v1.y);
            *reinterpret_cast<__half2*>(&Ch[(long long)r * CDIM + c]) =
                __halves2half2(h0, h1);
            *reinterpret_cast<__half2*>(&Ch[(long long)(r + 8) * CDIM + c]) =
                __halves2half2(h2, h3);
            if (Cl) {
                *reinterpret_cast<__half2*>(&Cl[(long long)r * CDIM + c]) =
                    __halves2half2(__float2half_rn(v0.x - __half2float(h0)),
                                   __float2half_rn(v0.y - __half2float(h1)));
                *reinterpret_cast<__half2*>(&Cl[(long long)(r + 8) * CDIM + c]) =
                    __halves2half2(__float2half_rn(v1.x - __half2float(h2)),
                                   __float2half_rn(v1.y - __half2float(h3)));
            }
        }
    }
}

// ---------------------------------------------------------------------------
// Fused fp32 -> fp16 hi/lo splits
// ---------------------------------------------------------------------------
__global__ __launch_bounds__(256) void split2_kernel(
    const float* __restrict__ x0, __half* __restrict__ h0o, __half* __restrict__ l0o,
    const float* __restrict__ x1, __half* __restrict__ h1o, __half* __restrict__ l1o,
    int n4)
{
    const int idx = blockIdx.x * 256 + threadIdx.x;
    if (idx >= n4) return;
    const float* x = blockIdx.y ? x1 : x0;
    __half* h = blockIdx.y ? h1o : h0o;
    __half* l = blockIdx.y ? l1o : l0o;
    const float4 v = reinterpret_cast<const float4*>(x)[idx];
    const __half a0 = __float2half_rn(v.x), a1 = __float2half_rn(v.y);
    const __half a2 = __float2half_rn(v.z), a3 = __float2half_rn(v.w);
    reinterpret_cast<__half2*>(h)[idx * 2]     = __halves2half2(a0, a1);
    reinterpret_cast<__half2*>(h)[idx * 2 + 1] = __halves2half2(a2, a3);
    reinterpret_cast<__half2*>(l)[idx * 2] = __halves2half2(
        __float2half_rn(v.x - __half2float(a0)),
        __float2half_rn(v.y - __half2float(a1)));
    reinterpret_cast<__half2*>(l)[idx * 2 + 1] = __halves2half2(
        __float2half_rn(v.z - __half2float(a2)),
        __float2half_rn(v.w - __half2float(a3)));
}

__global__ __launch_bounds__(256) void split3_kernel(
    const float* __restrict__ x0, __half* __restrict__ h0o, __half* __restrict__ l0o,
    const float* __restrict__ x1, __half* __restrict__ h1o, __half* __restrict__ l1o,
    const float* __restrict__ x2, __half* __restrict__ h2o, __half* __restrict__ l2o,
    int n4)
{
    const int idx = blockIdx.x * 256 + threadIdx.x;
    if (idx >= n4) return;
    const float* x = (blockIdx.y == 0) ? x0 : (blockIdx.y == 1) ? x1 : x2;
    __half* h = (blockIdx.y == 0) ? h0o : (blockIdx.y == 1) ? h1o : h2o;
    __half* l = (blockIdx.y == 0) ? l0o : (blockIdx.y == 1) ? l1o : l2o;
    const float4 v = reinterpret_cast<const float4*>(x)[idx];
    const __half a0 = __float2half_rn(v.x), a1 = __float2half_rn(v.y);
    const __half a2 = __float2half_rn(v.z), a3 = __float2half_rn(v.w);
    reinterpret_cast<__half2*>(h)[idx * 2]     = __halves2half2(a0, a1);
    reinterpret_cast<__half2*>(h)[idx * 2 + 1] = __halves2half2(a2, a3);
    reinterpret_cast<__half2*>(l)[idx * 2] = __halves2half2(
        __float2half_rn(v.x - __half2float(a0)),
        __float2half_rn(v.y - __half2float(a1)));
    reinterpret_cast<__half2*>(l)[idx * 2 + 1] = __halves2half2(
        __float2half_rn(v.z - __half2float(a2)),
        __float2half_rn(v.w - __half2float(a3)));
}

// ---------------------------------------------------------------------------
// Row softmax over TF, fp16 output (output GEMM is 1-pass)
// ---------------------------------------------------------------------------
__global__ __launch_bounds__(256) void softmax_h(
    const float* __restrict__ S, __half* __restrict__ H)
{
    const long long row = blockIdx.x;
    const float* p = S + row * (long long)TF;
    const int tid = threadIdx.x;
    __shared__ float red[32];

    float4 v0 = *reinterpret_cast<const float4*>(&p[tid * 8]);
    float4 v1 = *reinterpret_cast<const float4*>(&p[tid * 8 + 4]);

    float lmax = fmaxf(fmaxf(fmaxf(v0.x, v0.y), fmaxf(v0.z, v0.w)),
                       fmaxf(fmaxf(v1.x, v1.y), fmaxf(v1.z, v1.w)));
    #pragma unroll
    for (int o = 16; o; o >>= 1) lmax = fmaxf(lmax, __shfl_xor_sync(0xffffffffu, lmax, o));
    if ((tid & 31) == 0) red[tid >> 5] = lmax;
    __syncthreads();
    if (tid < 32) {
        float v = (tid < 8) ? red[tid] : -INFINITY;
        #pragma unroll
        for (int o = 4; o; o >>= 1) v = fmaxf(v, __shfl_xor_sync(0xffffffffu, v, o));
        if (tid == 0) red[0] = v;
    }
    __syncthreads();
    const float mx = red[0];
    __syncthreads();

    v0.x = __expf(v0.x - mx); v0.y = __expf(v0.y - mx);
    v0.z = __expf(v0.z - mx); v0.w = __expf(v0.w - mx);
    v1.x = __expf(v1.x - mx); v1.y = __expf(v1.y - mx);
    v1.z = __expf(v1.z - mx); v1.w = __expf(v1.w - mx);
    float lsum = (v0.x + v0.y + v0.z + v0.w) + (v1.x + v1.y + v1.z + v1.w);
    #pragma unroll
    for (int o = 16; o; o >>= 1) lsum += __shfl_xor_sync(0xffffffffu, lsum, o);
    if ((tid & 31) == 0) red[tid >> 5] = lsum;
    __syncthreads();
    if (tid < 32) {
        float v = (tid < 8) ? red[tid] : 0.0f;
        #pragma unroll
        for (int o = 4; o; o >>= 1) v += __shfl_xor_sync(0xffffffffu, v, o);
        if (tid == 0) red[0] = v;
    }
    __syncthreads();
    const float inv = 1.0f / red[0];

    __half* hp = H + row * (long long)TF + tid * 8;
    *reinterpret_cast<__half2*>(hp)     = __halves2half2(__float2half_rn(v0.x * inv), __float2half_rn(v0.y * inv));
    *reinterpret_cast<__half2*>(hp + 2) = __halves2half2(__float2half_rn(v0.z * inv), __float2half_rn(v0.w * inv));
    *reinterpret_cast<__half2*>(hp + 4) = __halves2half2(__float2half_rn(v1.x * inv), __float2half_rn(v1.y * inv));
    *reinterpret_cast<__half2*>(hp + 6) = __halves2half2(__float2half_rn(v1.z * inv), __float2half_rn(v1.w * inv));
}

// ---------------------------------------------------------------------------
// kernel_launch
// ---------------------------------------------------------------------------
extern "C" void kernel_launch(void* const* d_in, const int* in_sizes, int n_in,
                              void* d_out, int out_size)
{
    const float* q  = (const float*)d_in[0];
    const float* k  = (const float*)d_in[1];
    const float* Wq = (const float*)d_in[2];
    const float* bq = (const float*)d_in[3];
    const float* Wk = (const float*)d_in[4];
    const float* bk = (const float*)d_in[5];
    const float* Wv = (const float*)d_in[6];
    const float* bv = (const float*)d_in[7];
    float* out = (float*)d_out;

    void* p;
    cudaGetSymbolAddress(&p, g_sc);   float* sc  = (float*)p;
    cudaGetSymbolAddress(&p, g_qh);   __half* qh = (__half*)p;
    cudaGetSymbolAddress(&p, g_ql);   __half* ql = (__half*)p;
    cudaGetSymbolAddress(&p, g_kh);   __half* kh = (__half*)p;
    cudaGetSymbolAddress(&p, g_kl);   __half* kl = (__half*)p;
    cudaGetSymbolAddress(&p, g_Wqh);  __half* Wqh = (__half*)p;
    cudaGetSymbolAddress(&p, g_Wql);  __half* Wql = (__half*)p;
    cudaGetSymbolAddress(&p, g_Wkh);  __half* Wkh = (__half*)p;
    cudaGetSymbolAddress(&p, g_Wkl);  __half* Wkl = (__half*)p;
    cudaGetSymbolAddress(&p, g_Wvh);  __half* Wvh = (__half*)p;
    cudaGetSymbolAddress(&p, g_Wvl);  __half* Wvl = (__half*)p;
    cudaGetSymbolAddress(&p, g_qinh); __half* qinh = (__half*)p;
    cudaGetSymbolAddress(&p, g_qinl); __half* qinl = (__half*)p;
    cudaGetSymbolAddress(&p, g_kph);  __half* kph  = (__half*)p;
    cudaGetSymbolAddress(&p, g_kpl);  __half* kpl  = (__half*)p;
    cudaGetSymbolAddress(&p, g_vph);  __half* vph  = (__half*)p;
    cudaGetSymbolAddress(&p, g_sch);  __half* sch  = (__half*)p;

    cudaFuncSetAttribute(mma_gemm<3>, cudaFuncAttributeMaxDynamicSharedMemorySize, SMEM_GEMM);
    cudaFuncSetAttribute(mma_gemm<1>, cudaFuncAttributeMaxDynamicSharedMemorySize, SMEM_GEMM);
    cudaFuncSetAttribute(proj_gemm,   cudaFuncAttributeMaxDynamicSharedMemorySize, SMEM_GEMM);

    // 1. split inputs + weights to fp16 hi/lo (fused launches)
    {
        const int n4 = NELEM_QK / 4;
        split2_kernel<<<dim3(n4 / 256, 2), 256>>>(q, qh, ql, k, kh, kl, n4);
        const int w4 = CDIM * CDIM / 4;
        split3_kernel<<<dim3(w4 / 256, 3), 256>>>(Wq, Wqh, Wql,
                                                  Wk, Wkh, Wkl,
                                                  Wv, Wvh, Wvl, w4);
    }
    // 2. merged projections: z=0 q (3-pass), z=1 k (3-pass), z=2 v (2-pass)
    {
        const dim3 grd(CDIM / 128, (BATCH * THW) / 128, 3);
        proj_gemm<<<grd, 256, SMEM_GEMM>>>(qh, ql, kh, kl,
                                           Wqh, Wql, Wkh, Wkl, Wvh,
                                           bq, bk, bv,
                                           qinh, qinl, kph, kpl, vph);
    }
    // 3. scores (3-pass): qin (lda=CDIM) x raw-view kin[c][t] (B[k=c][n=t], ldb=TF)
    {
        const dim3 grd(TF / 128, THW / 128, BATCH);
        mma_gemm<3><<<grd, 256, SMEM_GEMM>>>(qinh, qinl, kph, kpl, nullptr, nullptr, nullptr,
                                             sc, nullptr, nullptr,
                                             CDIM, CDIM, TF, TF,
                                             (long long)THW * CDIM,
                                             (long long)TF * CDIM,
                                             (long long)THW * TF, 0);
    }
    // 4. softmax -> fp16
    softmax_h<<<BATCH * THW, 256>>>(sc, sch);
    // 5. output (1-pass fp16): attn (lda=TF) x vp[t][c] (B[k=t][n=c], ldb=CDIM)
    //    + residual reconstructed from qinh+qinl
    {
        const dim3 grd(CDIM / 128, THW / 128, BATCH);
        mma_gemm<1><<<grd, 256, SMEM_GEMM>>>(sch, nullptr, vph, nullptr, nullptr,
                                             qinh, qinl,
                                             out, nullptr, nullptr,
                                             TF, TF, CDIM, CDIM,
                                             (long long)THW * TF,
                                             (long long)TF * CDIM,
                                             (long long)THW * CDIM,
                                             (long long)THW * CDIM);
    }
}